// round 14
// baseline (speedup 1.0000x reference)
#include <cuda_runtime.h>
#include <cuda_fp16.h>
#include <cstdint>

// ============================================================================
// TensorDense via explicit-W:  out = relu(x @ W + bias)
//   W[(i,j,k),(a,b,c)] = sum_q (sum_p c1[i,a,p] c2[j,b,p,q]) c3[k,c,q]
// Single-product fp16 GEMM (mma.sync m16n8k16, fp32 accum) at the measured
// legacy-HMMA instruction-rate ceiling (~242us). Prep is ONE launch:
// blocks [0,1024) fuse w12+assemble per (i,j,c-quarter) entirely in
// smem+registers (no W12 global round-trip); blocks [1024,2048) convert x.
// ============================================================================

#define MODE 16
#define KDIM 4096
#define NDIM 4096
#define BATCH 2048

__device__ __half g_xh[(size_t)BATCH * KDIM];
__device__ __half g_wh[(size_t)NDIM * KDIM];        // W^T [n][k], fp16

// ---------------------------------------------------------------------------
// helpers (sm_80/sm_90-era only; ptxas targets bare sm_103)
// ---------------------------------------------------------------------------
__device__ __forceinline__ uint32_t smem_u32(const void* p) {
    uint32_t a;
    asm("{ .reg .u64 t; cvta.to.shared.u64 t, %1; cvt.u32.u64 %0, t; }"
        : "=r"(a) : "l"(p));
    return a;
}
__device__ __forceinline__ void cp_async16(uint32_t s, const void* g) {
    asm volatile("cp.async.cg.shared.global [%0], [%1], 16;" :: "r"(s), "l"(g));
}
#define CP_COMMIT() asm volatile("cp.async.commit_group;" ::: "memory")
#define CP_WAIT1()  asm volatile("cp.async.wait_group 1;"  ::: "memory")

__device__ __forceinline__ void ldmx4(uint32_t* r, uint32_t addr) {
    asm volatile("ldmatrix.sync.aligned.m8n8.x4.shared.b16 {%0,%1,%2,%3}, [%4];"
                 : "=r"(r[0]), "=r"(r[1]), "=r"(r[2]), "=r"(r[3]) : "r"(addr));
}
__device__ __forceinline__ void mma_f16(float* c, const uint32_t* a,
                                        uint32_t b0, uint32_t b1) {
    asm volatile(
        "mma.sync.aligned.m16n8k16.row.col.f32.f16.f16.f32 "
        "{%0,%1,%2,%3}, {%4,%5,%6,%7}, {%8,%9}, {%0,%1,%2,%3};"
        : "+f"(c[0]), "+f"(c[1]), "+f"(c[2]), "+f"(c[3])
        : "r"(a[0]), "r"(a[1]), "r"(a[2]), "r"(a[3]), "r"(b0), "r"(b1));
}
__device__ __forceinline__ uint32_t h2_as_u32(__half2 h) {
    uint32_t u;
    memcpy(&u, &h, 4);
    return u;
}

// ---------------------------------------------------------------------------
// Prep (ONE launch):
//  blocks [0,1024): per (ij, c-quarter): stage c1/c2/c3, compute W12 row in
//    registers (1024 FMA), assemble 4 fp16 W^T row-chunks, store.
//  blocks [1024,2048): x -> fp16, 4 uint4 packs per thread, loads batched.
// SMEM (floats): sc2[16][1028] | sc1[512] | sc3[2048]  = 76032 bytes.
// Stride 1028: bank shift 4 per b-row -> <=2-way LDS conflicts (vs 8-way
// at stride 1040, which sank the R8 fused attempt).
// ---------------------------------------------------------------------------
#define SC2S 1028
#define PREP_SMEM_FLOATS (16 * SC2S + 512 + 2048)
#define PREP_DYN_BYTES (PREP_SMEM_FLOATS * 4)      // 76032

__global__ void prep_kernel(const float* __restrict__ x,
                            const float* __restrict__ c1,
                            const float* __restrict__ c2,
                            const float* __restrict__ c3) {
    extern __shared__ __align__(16) float sdyn[];
    const int tid = threadIdx.x;

    if (blockIdx.x >= 1024) {
        // ---- x conversion: 1024 blocks x 256 thr x 4 packs (MLP 8) ----
        const size_t blk = (size_t)(blockIdx.x - 1024);
        const size_t p0 = blk * 1024 + tid;
        float4 v[8];
#pragma unroll
        for (int u = 0; u < 4; ++u) {
            const size_t p = p0 + (size_t)u * 256;
            v[u * 2 + 0] = reinterpret_cast<const float4*>(x)[p * 2 + 0];
            v[u * 2 + 1] = reinterpret_cast<const float4*>(x)[p * 2 + 1];
        }
#pragma unroll
        for (int u = 0; u < 4; ++u) {
            uint4 o;
            o.x = h2_as_u32(__floats2half2_rn(v[u * 2].x,     v[u * 2].y));
            o.y = h2_as_u32(__floats2half2_rn(v[u * 2].z,     v[u * 2].w));
            o.z = h2_as_u32(__floats2half2_rn(v[u * 2 + 1].x, v[u * 2 + 1].y));
            o.w = h2_as_u32(__floats2half2_rn(v[u * 2 + 1].z, v[u * 2 + 1].w));
            reinterpret_cast<uint4*>(g_xh)[p0 + (size_t)u * 256] = o;
        }
        return;
    }

    // ---- fused w12 + assemble: CTA per (ij, cg), thread per (a,b) ----
    const int ij = blockIdx.x >> 2;
    const int cg = blockIdx.x & 3;
    const int i = ij >> 4, j = ij & 15;
    const int a = tid >> 4, b = tid & 15;

    float* sc2 = sdyn;                       // [16][SC2S]
    float* sc1 = sdyn + 16 * SC2S;           // [512]
    float* sc3 = sc1 + 512;                  // [2048]

    // stage c2 j-slice: 16 jb-rows x 1024 floats
    {
        const float4* src = reinterpret_cast<const float4*>(c2 + (size_t)j * 16384);
#pragma unroll
        for (int u = 0; u < 16; ++u) {
            const int e = u * 256 + tid;              // float4 idx 0..4095
            const int bb = e >> 8, rest = e & 255;
            reinterpret_cast<float4*>(sc2 + bb * SC2S)[rest] = src[e];
        }
    }
    // stage c1 i-slice: 512 floats
    if (tid < 128) {
        reinterpret_cast<float4*>(sc1)[tid] =
            reinterpret_cast<const float4*>(c1 + (size_t)i * 512)[tid];
    }
    // stage c3 rows c = cg*4..cg*4+3 for all kz: 512 float4
    {
        const float4* c3g = reinterpret_cast<const float4*>(c3);
        float4* dst = reinterpret_cast<float4*>(sc3);
#pragma unroll
        for (int u = 0; u < 2; ++u) {
            const int e4 = u * 256 + tid;             // 0..511
            const int kz = e4 >> 5, rem4 = e4 & 31;
            dst[e4] = c3g[kz * 128 + cg * 32 + rem4];
        }
    }
    __syncthreads();

    // W12[q] = sum_p c1[ia][p] * c2[jb][p][q]   (registers)
    float w12v[32];
#pragma unroll
    for (int q = 0; q < 32; ++q) w12v[q] = 0.f;
    {
        const float* c1row = sc1 + a * 32;
        const float* c2row = sc2 + b * SC2S;
#pragma unroll
        for (int p = 0; p < 32; ++p) {
            const float cp = c1row[p];
            const float4* c2q = reinterpret_cast<const float4*>(c2row + p * 32);
#pragma unroll
            for (int q4 = 0; q4 < 8; ++q4) {
                float4 w = c2q[q4];
                w12v[q4 * 4 + 0] = fmaf(cp, w.x, w12v[q4 * 4 + 0]);
                w12v[q4 * 4 + 1] = fmaf(cp, w.y, w12v[q4 * 4 + 1]);
                w12v[q4 * 4 + 2] = fmaf(cp, w.z, w12v[q4 * 4 + 2]);
                w12v[q4 * 4 + 3] = fmaf(cp, w.w, w12v[q4 * 4 + 3]);
            }
        }
    }

    // assemble 4 c-rows: wh[(ab*16+c)][ij*16+kz]
    const float4* sc3v = reinterpret_cast<const float4*>(sc3);
    const float4* w12q = reinterpret_cast<const float4*>(w12v);
#pragma unroll
    for (int cc = 0; cc < 4; ++cc) {
        float acc[16];
#pragma unroll
        for (int kz = 0; kz < 16; ++kz) acc[kz] = 0.f;
#pragma unroll
        for (int q4 = 0; q4 < 8; ++q4) {
            const float4 w = w12q[q4];
#pragma unroll
            for (int kz = 0; kz < 16; ++kz) {
                float4 cv = sc3v[(kz * 4 + cc) * 8 + q4];   // broadcast
                acc[kz] = fmaf(w.x, cv.x, acc[kz]);
                acc[kz] = fmaf(w.y, cv.y, acc[kz]);
                acc[kz] = fmaf(w.z, cv.z, acc[kz]);
                acc[kz] = fmaf(w.w, cv.w, acc[kz]);
            }
        }
        __half2 hv[8];
#pragma unroll
        for (int u = 0; u < 8; ++u)
            hv[u] = __floats2half2_rn(acc[u * 2], acc[u * 2 + 1]);
        __half* dst = g_wh + (size_t)(tid * 16 + cg * 4 + cc) * KDIM + ij * 16;
        uint4 o0, o1;
        memcpy(&o0, &hv[0], 16);
        memcpy(&o1, &hv[4], 16);
        reinterpret_cast<uint4*>(dst)[0] = o0;
        reinterpret_cast<uint4*>(dst)[1] = o1;
    }
}

// ---------------------------------------------------------------------------
// GEMM: single-product fp16 (best measured mainloop, 242.4us) — unchanged.
// CTA tile 128x128, 4 warps (2m x 2n), warp tile 64x64, BK=64,
// 3-stage cp.async ring, one sync/stage, 2 CTAs/SM.
// SMEM rows: 128B data + 16B pad = 144B (conflict-free ldmatrix).
// ---------------------------------------------------------------------------
#define BM 128
#define BN 128
#define ROWB 144
#define ARR_BYTES (128 * ROWB)            // 18432
#define STAGE_BYTES (2 * ARR_BYTES)       // xh | wh = 36864
#define STAGES 3
#define DYN_BYTES (STAGES * STAGE_BYTES)  // 110592

__global__ __launch_bounds__(128, 2)
void tt_gemm_f16(const float* __restrict__ bias, float* __restrict__ C) {
    extern __shared__ __align__(16) char dyn[];
    const uint32_t dynU = smem_u32(dyn);

    const int tid = threadIdx.x;
    const int wid = tid >> 5;
    const int lid = tid & 31;
    const int warp_m = wid & 1;      // 2 m-groups of 64 rows
    const int warp_n = wid >> 1;     // 2 n-groups of 64 cols
    const int m0 = blockIdx.y * BM;
    const int n0 = blockIdx.x * BN;

    const char* xh = (const char*)g_xh;
    const char* wh = (const char*)g_wh;

    uint32_t sOff[8];
    size_t gAOff[8], gBOff[8];
#pragma unroll
    for (int u = 0; u < 8; ++u) {
        const int ci = u * 128 + tid;
        const int r = ci >> 3, ch = (ci & 7) * 16;
        sOff[u] = (uint32_t)(r * ROWB + ch);
        gAOff[u] = (size_t)(m0 + r) * (KDIM * 2) + ch;
        gBOff[u] = (size_t)(n0 + r) * (KDIM * 2) + ch;
    }

    float acc[4][8][4];
#pragma unroll
    for (int a = 0; a < 4; ++a)
#pragma unroll
        for (int b = 0; b < 8; ++b)
#pragma unroll
            for (int c = 0; c < 4; ++c) acc[a][b][c] = 0.f;

    const uint32_t lmRow = (uint32_t)(lid & 15);
    const uint32_t lmCol = (uint32_t)((lid >> 4) * 16);
    const uint32_t aLM = (uint32_t)((warp_m * 64 + lmRow) * ROWB) + lmCol;
    const uint32_t bLM = (uint32_t)((warp_n * 64 + lmRow) * ROWB) + lmCol;

    auto load_stage = [&](int kt) {
        const uint32_t sb = dynU + (uint32_t)(kt % STAGES) * STAGE_BYTES;
        const size_t ko = (size_t)kt * 128;   // 64 halves = 128B along k
#pragma unroll
        for (int u = 0; u < 8; ++u) {
            cp_async16(sb + sOff[u],             xh + gAOff[u] + ko);
            cp_async16(sb + ARR_BYTES + sOff[u], wh + gBOff[u] + ko);
        }
    };

    load_stage(0); CP_COMMIT();
    load_stage(1); CP_COMMIT();

    const int numK = KDIM / 64;      // 64 stages
    for (int kt = 0; kt < numK; ++kt) {
        CP_WAIT1();
        __syncthreads();             // publish stage kt

        if (kt + 2 < numK) load_stage(kt + 2);
        CP_COMMIT();

        const uint32_t sb = dynU + (uint32_t)(kt % STAGES) * STAGE_BYTES;
        const uint32_t aB = sb + aLM;
        const uint32_t bB = sb + ARR_BYTES + bLM;

#pragma unroll
        for (int ks = 0; ks < 4; ++ks) {             // four k16 steps
            const uint32_t kb = (uint32_t)(ks * 32); // 16 halves = 32B
            uint32_t ah[4][4];
#pragma unroll
            for (int mt = 0; mt < 4; ++mt)
                ldmx4(ah[mt], aB + (uint32_t)(mt * 16 * ROWB) + kb);
            uint32_t bh[4][4];
#pragma unroll
            for (int bt = 0; bt < 4; ++bt)
                ldmx4(bh[bt], bB + (uint32_t)(bt * 16 * ROWB) + kb);
#pragma unroll
            for (int mt = 0; mt < 4; ++mt) {
#pragma unroll
                for (int nt = 0; nt < 8; ++nt) {
                    const int bt = nt >> 1, o = nt & 1;
                    mma_f16(acc[mt][nt], ah[mt], bh[bt][o], bh[bt][o + 2]);
                }
            }
        }
    }

    // epilogue: bias + relu, float2 stores
    const int g = lid >> 2, t4 = lid & 3;
    float bb[8][2];
#pragma unroll
    for (int nt = 0; nt < 8; ++nt) {
        const int col = n0 + warp_n * 64 + nt * 8 + t4 * 2;
        bb[nt][0] = bias[col];
        bb[nt][1] = bias[col + 1];
    }
#pragma unroll
    for (int mt = 0; mt < 4; ++mt) {
        const int row = m0 + warp_m * 64 + mt * 16 + g;
#pragma unroll
        for (int nt = 0; nt < 8; ++nt) {
            const int col = n0 + warp_n * 64 + nt * 8 + t4 * 2;
            float2 v0, v1;
            v0.x = fmaxf(acc[mt][nt][0] + bb[nt][0], 0.f);
            v0.y = fmaxf(acc[mt][nt][1] + bb[nt][1], 0.f);
            v1.x = fmaxf(acc[mt][nt][2] + bb[nt][0], 0.f);
            v1.y = fmaxf(acc[mt][nt][3] + bb[nt][1], 0.f);
            *reinterpret_cast<float2*>(&C[(size_t)row * NDIM + col]) = v0;
            *reinterpret_cast<float2*>(&C[(size_t)(row + 8) * NDIM + col]) = v1;
        }
    }
}

// ---------------------------------------------------------------------------
// Launch
// ---------------------------------------------------------------------------
extern "C" void kernel_launch(void* const* d_in, const int* in_sizes, int n_in,
                              void* d_out, int out_size) {
    const float* x    = (const float*)d_in[0];
    const float* c1   = (const float*)d_in[1];
    const float* c2   = (const float*)d_in[2];
    const float* c3   = (const float*)d_in[3];
    const float* bias = (const float*)d_in[4];
    float* out = (float*)d_out;
    (void)in_sizes; (void)n_in; (void)out_size;

    cudaFuncSetAttribute(prep_kernel,
                         cudaFuncAttributeMaxDynamicSharedMemorySize, PREP_DYN_BYTES);
    cudaFuncSetAttribute(tt_gemm_f16,
                         cudaFuncAttributeMaxDynamicSharedMemorySize, DYN_BYTES);

    prep_kernel<<<2048, 256, PREP_DYN_BYTES>>>(x, c1, c2, c3);

    dim3 grid(NDIM / BN, BATCH / BM);   // (32, 16) = 512 CTAs
    tt_gemm_f16<<<grid, 128, DYN_BYTES>>>(bias, out);
}

// round 15
// speedup vs baseline: 1.0250x; 1.0250x over previous
#include <cuda_runtime.h>
#include <cuda_fp16.h>
#include <cstdint>

// ============================================================================
// TensorDense via explicit-W:  out = relu(x @ W + bias)
//   W[(i,j,k),(a,b,c)] = sum_q (sum_p c1[i,a,p] c2[j,b,p,q]) c3[k,c,q]
// Single-product fp16 GEMM (mma.sync m16n8k16, fp32 accum) at the measured
// legacy-HMMA rate wall (16.3 cyc/HMMA/SMSP, ~99% pipe busy: 242.7us floor).
// This round trims the prep path: MLP-8 batched x-conversion and a
// 2048-block assemble (2 c-rows per thread).
// ============================================================================

#define MODE 16
#define KDIM 4096
#define NDIM 4096
#define BATCH 2048

__device__ float  g_W12[256 * 256 * 32];            // [ia][jb][q]  8MB
__device__ __half g_xh[(size_t)BATCH * KDIM];
__device__ __half g_wh[(size_t)NDIM * KDIM];        // W^T [n][k], fp16

// ---------------------------------------------------------------------------
// helpers (sm_80/sm_90-era only; ptxas targets bare sm_103)
// ---------------------------------------------------------------------------
__device__ __forceinline__ uint32_t smem_u32(const void* p) {
    uint32_t a;
    asm("{ .reg .u64 t; cvta.to.shared.u64 t, %1; cvt.u32.u64 %0, t; }"
        : "=r"(a) : "l"(p));
    return a;
}
__device__ __forceinline__ void cp_async16(uint32_t s, const void* g) {
    asm volatile("cp.async.cg.shared.global [%0], [%1], 16;" :: "r"(s), "l"(g));
}
#define CP_COMMIT() asm volatile("cp.async.commit_group;" ::: "memory")
#define CP_WAIT1()  asm volatile("cp.async.wait_group 1;"  ::: "memory")

__device__ __forceinline__ void ldmx4(uint32_t* r, uint32_t addr) {
    asm volatile("ldmatrix.sync.aligned.m8n8.x4.shared.b16 {%0,%1,%2,%3}, [%4];"
                 : "=r"(r[0]), "=r"(r[1]), "=r"(r[2]), "=r"(r[3]) : "r"(addr));
}
__device__ __forceinline__ void mma_f16(float* c, const uint32_t* a,
                                        uint32_t b0, uint32_t b1) {
    asm volatile(
        "mma.sync.aligned.m16n8k16.row.col.f32.f16.f16.f32 "
        "{%0,%1,%2,%3}, {%4,%5,%6,%7}, {%8,%9}, {%0,%1,%2,%3};"
        : "+f"(c[0]), "+f"(c[1]), "+f"(c[2]), "+f"(c[3])
        : "r"(a[0]), "r"(a[1]), "r"(a[2]), "r"(a[3]), "r"(b0), "r"(b1));
}
__device__ __forceinline__ uint32_t h2_as_u32(__half2 h) {
    uint32_t u;
    memcpy(&u, &h, 4);
    return u;
}

// ---------------------------------------------------------------------------
// Launch 1: blocks [0,256): W12[ia][jb][q] (CTA per jb, thread per ia);
//           blocks [256,1280): x -> fp16, 4 packs/thread, ALL loads batched.
// ---------------------------------------------------------------------------
__global__ void prep1_kernel(const float* __restrict__ x,
                             const float* __restrict__ c1,
                             const float* __restrict__ c2) {
    const int tid = threadIdx.x;

    if (blockIdx.x >= 256) {
        // ---- x conversion: 1024 blocks x 256 thr x 4 uint4 packs (MLP 8) --
        const size_t p0 = (size_t)(blockIdx.x - 256) * 1024 + tid;
        float4 v[8];
#pragma unroll
        for (int u = 0; u < 4; ++u) {
            const size_t p = p0 + (size_t)u * 256;
            v[u * 2 + 0] = reinterpret_cast<const float4*>(x)[p * 2 + 0];
            v[u * 2 + 1] = reinterpret_cast<const float4*>(x)[p * 2 + 1];
        }
#pragma unroll
        for (int u = 0; u < 4; ++u) {
            uint4 o;
            o.x = h2_as_u32(__floats2half2_rn(v[u * 2].x,     v[u * 2].y));
            o.y = h2_as_u32(__floats2half2_rn(v[u * 2].z,     v[u * 2].w));
            o.z = h2_as_u32(__floats2half2_rn(v[u * 2 + 1].x, v[u * 2 + 1].y));
            o.w = h2_as_u32(__floats2half2_rn(v[u * 2 + 1].z, v[u * 2 + 1].w));
            reinterpret_cast<uint4*>(g_xh)[p0 + (size_t)u * 256] = o;
        }
        return;
    }

    // ---- W12: CTA per jb, thread per ia ----
    __shared__ float sc2[1024];
    const int jb = blockIdx.x;

    reinterpret_cast<float4*>(sc2)[tid] =
        reinterpret_cast<const float4*>(c2 + (size_t)jb * 1024)[tid];

    float4 c1v[8];
    const float4* c1p = reinterpret_cast<const float4*>(c1 + tid * 32);
#pragma unroll
    for (int u = 0; u < 8; ++u) c1v[u] = c1p[u];
    __syncthreads();

    float4 acc[8];
#pragma unroll
    for (int u = 0; u < 8; ++u) acc[u] = make_float4(0.f, 0.f, 0.f, 0.f);

    const float4* sc2v = reinterpret_cast<const float4*>(sc2);
    const float* c1s = reinterpret_cast<const float*>(c1v);
#pragma unroll
    for (int p = 0; p < 32; ++p) {
        const float cp = c1s[p];
#pragma unroll
        for (int q4 = 0; q4 < 8; ++q4) {
            float4 w = sc2v[p * 8 + q4];          // warp broadcast
            acc[q4].x = fmaf(cp, w.x, acc[q4].x);
            acc[q4].y = fmaf(cp, w.y, acc[q4].y);
            acc[q4].z = fmaf(cp, w.z, acc[q4].z);
            acc[q4].w = fmaf(cp, w.w, acc[q4].w);
        }
    }
    float4* outp = reinterpret_cast<float4*>(g_W12 + ((size_t)tid * 256 + jb) * 32);
#pragma unroll
    for (int u = 0; u < 8; ++u) outp[u] = acc[u];
}

// ---------------------------------------------------------------------------
// Launch 2: assemble W^T fp16, CTA per (i,j,c-eighth) = 2048 blocks.
//   wh[(ab*16+c)][ij*16+kz] = fp16( sum_q W12[ia][jb][q] * c3[kz][c][q] )
// Each CTA stages its 2 c-rows of c3 for all kz (1024 floats).
// ---------------------------------------------------------------------------
__global__ void assemble_w_kernel(const float* __restrict__ c3) {
    __shared__ float sc3[1024];               // [kz][cc][q] for 2 c's
    const int ij = blockIdx.x >> 3;
    const int cg = blockIdx.x & 7;            // c-eighth: c = cg*2 + cc
    const int tid = threadIdx.x;              // ab
    const int a = tid >> 4, b = tid & 15;
    const int i = ij >> 4, j = ij & 15;

    // stage c3 rows c = cg*2, cg*2+1 for all kz: 256 float4, one per thread.
    // dst index tid = kz*16 + cc*8 + q4  (kz = tid>>4, cc = (tid>>3)&1, q4 = tid&7)
    {
        const float4* c3g = reinterpret_cast<const float4*>(c3);
        const int kz = tid >> 4, cc = (tid >> 3) & 1, q4 = tid & 7;
        reinterpret_cast<float4*>(sc3)[tid] =
            c3g[(kz * 16 + cg * 2 + cc) * 8 + q4];
    }

    // W12 row for this (ia, jb) in registers
    float4 w12q[8];
    const float4* wp = reinterpret_cast<const float4*>(
        g_W12 + ((size_t)(i * 16 + a) * 256 + (j * 16 + b)) * 32);
#pragma unroll
    for (int u = 0; u < 8; ++u) w12q[u] = wp[u];
    __syncthreads();

    const float4* sc3v = reinterpret_cast<const float4*>(sc3);
#pragma unroll
    for (int cc = 0; cc < 2; ++cc) {
        float acc[16];
#pragma unroll
        for (int kz = 0; kz < 16; ++kz) acc[kz] = 0.f;
#pragma unroll
        for (int q4 = 0; q4 < 8; ++q4) {
            const float4 w = w12q[q4];
#pragma unroll
            for (int kz = 0; kz < 16; ++kz) {
                float4 cv = sc3v[(kz * 2 + cc) * 8 + q4];   // warp broadcast
                acc[kz] = fmaf(w.x, cv.x, acc[kz]);
                acc[kz] = fmaf(w.y, cv.y, acc[kz]);
                acc[kz] = fmaf(w.z, cv.z, acc[kz]);
                acc[kz] = fmaf(w.w, cv.w, acc[kz]);
            }
        }
        __half2 hv[8];
#pragma unroll
        for (int u = 0; u < 8; ++u)
            hv[u] = __floats2half2_rn(acc[u * 2], acc[u * 2 + 1]);
        __half* dst = g_wh + (size_t)(tid * 16 + cg * 2 + cc) * KDIM + ij * 16;
        uint4 o0, o1;
        memcpy(&o0, &hv[0], 16);
        memcpy(&o1, &hv[4], 16);
        reinterpret_cast<uint4*>(dst)[0] = o0;
        reinterpret_cast<uint4*>(dst)[1] = o1;
    }
}

// ---------------------------------------------------------------------------
// Launch 3: single-product fp16 GEMM (byte-identical to the measured
// 242.7us floor). CTA tile 128x128, 4 warps (2m x 2n), warp tile 64x64,
// BK=64, 3-stage cp.async ring, one sync/stage, 2 CTAs/SM.
// SMEM rows: 128B data + 16B pad = 144B (conflict-free ldmatrix).
// ---------------------------------------------------------------------------
#define BM 128
#define BN 128
#define ROWB 144
#define ARR_BYTES (128 * ROWB)            // 18432
#define STAGE_BYTES (2 * ARR_BYTES)       // xh | wh = 36864
#define STAGES 3
#define DYN_BYTES (STAGES * STAGE_BYTES)  // 110592

__global__ __launch_bounds__(128, 2)
void tt_gemm_f16(const float* __restrict__ bias, float* __restrict__ C) {
    extern __shared__ __align__(16) char dyn[];
    const uint32_t dynU = smem_u32(dyn);

    const int tid = threadIdx.x;
    const int wid = tid >> 5;
    const int lid = tid & 31;
    const int warp_m = wid & 1;      // 2 m-groups of 64 rows
    const int warp_n = wid >> 1;     // 2 n-groups of 64 cols
    const int m0 = blockIdx.y * BM;
    const int n0 = blockIdx.x * BN;

    const char* xh = (const char*)g_xh;
    const char* wh = (const char*)g_wh;

    uint32_t sOff[8];
    size_t gAOff[8], gBOff[8];
#pragma unroll
    for (int u = 0; u < 8; ++u) {
        const int ci = u * 128 + tid;
        const int r = ci >> 3, ch = (ci & 7) * 16;
        sOff[u] = (uint32_t)(r * ROWB + ch);
        gAOff[u] = (size_t)(m0 + r) * (KDIM * 2) + ch;
        gBOff[u] = (size_t)(n0 + r) * (KDIM * 2) + ch;
    }

    float acc[4][8][4];
#pragma unroll
    for (int a = 0; a < 4; ++a)
#pragma unroll
        for (int b = 0; b < 8; ++b)
#pragma unroll
            for (int c = 0; c < 4; ++c) acc[a][b][c] = 0.f;

    const uint32_t lmRow = (uint32_t)(lid & 15);
    const uint32_t lmCol = (uint32_t)((lid >> 4) * 16);
    const uint32_t aLM = (uint32_t)((warp_m * 64 + lmRow) * ROWB) + lmCol;
    const uint32_t bLM = (uint32_t)((warp_n * 64 + lmRow) * ROWB) + lmCol;

    auto load_stage = [&](int kt) {
        const uint32_t sb = dynU + (uint32_t)(kt % STAGES) * STAGE_BYTES;
        const size_t ko = (size_t)kt * 128;   // 64 halves = 128B along k
#pragma unroll
        for (int u = 0; u < 8; ++u) {
            cp_async16(sb + sOff[u],             xh + gAOff[u] + ko);
            cp_async16(sb + ARR_BYTES + sOff[u], wh + gBOff[u] + ko);
        }
    };

    load_stage(0); CP_COMMIT();
    load_stage(1); CP_COMMIT();

    const int numK = KDIM / 64;      // 64 stages
    for (int kt = 0; kt < numK; ++kt) {
        CP_WAIT1();
        __syncthreads();             // publish stage kt

        if (kt + 2 < numK) load_stage(kt + 2);
        CP_COMMIT();

        const uint32_t sb = dynU + (uint32_t)(kt % STAGES) * STAGE_BYTES;
        const uint32_t aB = sb + aLM;
        const uint32_t bB = sb + ARR_BYTES + bLM;

#pragma unroll
        for (int ks = 0; ks < 4; ++ks) {             // four k16 steps
            const uint32_t kb = (uint32_t)(ks * 32); // 16 halves = 32B
            uint32_t ah[4][4];
#pragma unroll
            for (int mt = 0; mt < 4; ++mt)
                ldmx4(ah[mt], aB + (uint32_t)(mt * 16 * ROWB) + kb);
            uint32_t bh[4][4];
#pragma unroll
            for (int bt = 0; bt < 4; ++bt)
                ldmx4(bh[bt], bB + (uint32_t)(bt * 16 * ROWB) + kb);
#pragma unroll
            for (int mt = 0; mt < 4; ++mt) {
#pragma unroll
                for (int nt = 0; nt < 8; ++nt) {
                    const int bt = nt >> 1, o = nt & 1;
                    mma_f16(acc[mt][nt], ah[mt], bh[bt][o], bh[bt][o + 2]);
                }
            }
        }
    }

    // epilogue: bias + relu, float2 stores
    const int g = lid >> 2, t4 = lid & 3;
    float bb[8][2];
#pragma unroll
    for (int nt = 0; nt < 8; ++nt) {
        const int col = n0 + warp_n * 64 + nt * 8 + t4 * 2;
        bb[nt][0] = bias[col];
        bb[nt][1] = bias[col + 1];
    }
#pragma unroll
    for (int mt = 0; mt < 4; ++mt) {
        const int row = m0 + warp_m * 64 + mt * 16 + g;
#pragma unroll
        for (int nt = 0; nt < 8; ++nt) {
            const int col = n0 + warp_n * 64 + nt * 8 + t4 * 2;
            float2 v0, v1;
            v0.x = fmaxf(acc[mt][nt][0] + bb[nt][0], 0.f);
            v0.y = fmaxf(acc[mt][nt][1] + bb[nt][1], 0.f);
            v1.x = fmaxf(acc[mt][nt][2] + bb[nt][0], 0.f);
            v1.y = fmaxf(acc[mt][nt][3] + bb[nt][1], 0.f);
            *reinterpret_cast<float2*>(&C[(size_t)row * NDIM + col]) = v0;
            *reinterpret_cast<float2*>(&C[(size_t)(row + 8) * NDIM + col]) = v1;
        }
    }
}

// ---------------------------------------------------------------------------
// Launch
// ---------------------------------------------------------------------------
extern "C" void kernel_launch(void* const* d_in, const int* in_sizes, int n_in,
                              void* d_out, int out_size) {
    const float* x    = (const float*)d_in[0];
    const float* c1   = (const float*)d_in[1];
    const float* c2   = (const float*)d_in[2];
    const float* c3   = (const float*)d_in[3];
    const float* bias = (const float*)d_in[4];
    float* out = (float*)d_out;
    (void)in_sizes; (void)n_in; (void)out_size;

    cudaFuncSetAttribute(tt_gemm_f16,
                         cudaFuncAttributeMaxDynamicSharedMemorySize, DYN_BYTES);

    prep1_kernel<<<256 + 1024, 256>>>(x, c1, c2);   // w12 + batched cvt
    assemble_w_kernel<<<2048, 256>>>(c3);

    dim3 grid(NDIM / BN, BATCH / BM);   // (32, 16) = 512 CTAs
    tt_gemm_f16<<<grid, 128, DYN_BYTES>>>(bias, out);
}

// round 17
// speedup vs baseline: 1.0575x; 1.0317x over previous
#include <cuda_runtime.h>
#include <cuda_fp16.h>
#include <cstdint>

// ============================================================================
// TensorDense via explicit-W:  out = relu(x @ W + bias)
//   W[(i,j,k),(a,b,c)] = sum_q (sum_p c1[i,a,p] c2[j,b,p,q]) c3[k,c,q]
// GEMM: single-product fp16 mma.sync (fp32 accum) at the measured HMMA rate
// wall (16.3 cyc/HMMA/SMSP, 242.7us). Prep is ONE launch: blocks [0,256)
// each own one (i,j) pair and do c2/c1/c3 staging + w12 + all-16-c assemble
// self-contained (1x staging, conflict-free strides); blocks [256,1280)
// convert x -> fp16. Two launches total.
// R16 bug fixed: sc3 must hold the FULL c3 (8192 floats, not 2048) since the
// assemble loop covers all 16 c rows.
// ============================================================================

#define MODE 16
#define KDIM 4096
#define NDIM 4096
#define BATCH 2048

__device__ __half g_xh[(size_t)BATCH * KDIM];
__device__ __half g_wh[(size_t)NDIM * KDIM];        // W^T [n][k], fp16

// ---------------------------------------------------------------------------
// helpers (sm_80/sm_90-era only; ptxas targets bare sm_103)
// ---------------------------------------------------------------------------
__device__ __forceinline__ uint32_t smem_u32(const void* p) {
    uint32_t a;
    asm("{ .reg .u64 t; cvta.to.shared.u64 t, %1; cvt.u32.u64 %0, t; }"
        : "=r"(a) : "l"(p));
    return a;
}
__device__ __forceinline__ void cp_async16(uint32_t s, const void* g) {
    asm volatile("cp.async.cg.shared.global [%0], [%1], 16;" :: "r"(s), "l"(g));
}
#define CP_COMMIT() asm volatile("cp.async.commit_group;" ::: "memory")
#define CP_WAIT1()  asm volatile("cp.async.wait_group 1;"  ::: "memory")

__device__ __forceinline__ void ldmx4(uint32_t* r, uint32_t addr) {
    asm volatile("ldmatrix.sync.aligned.m8n8.x4.shared.b16 {%0,%1,%2,%3}, [%4];"
                 : "=r"(r[0]), "=r"(r[1]), "=r"(r[2]), "=r"(r[3]) : "r"(addr));
}
__device__ __forceinline__ void mma_f16(float* c, const uint32_t* a,
                                        uint32_t b0, uint32_t b1) {
    asm volatile(
        "mma.sync.aligned.m16n8k16.row.col.f32.f16.f16.f32 "
        "{%0,%1,%2,%3}, {%4,%5,%6,%7}, {%8,%9}, {%0,%1,%2,%3};"
        : "+f"(c[0]), "+f"(c[1]), "+f"(c[2]), "+f"(c[3])
        : "r"(a[0]), "r"(a[1]), "r"(a[2]), "r"(a[3]), "r"(b0), "r"(b1));
}
__device__ __forceinline__ uint32_t h2_as_u32(__half2 h) {
    uint32_t u;
    memcpy(&u, &h, 4);
    return u;
}

// ---------------------------------------------------------------------------
// Prep (ONE launch):
//  blocks [0,256): CTA per (i,j), thread per (a,b):
//    stage c2 j-slice (16x1024 @ stride 1028: LDS.128 phase-conflict-free),
//    c1 i-slice (512), c3 FULL (8192 floats); then W12 row in registers
//    (1024 FMA), then assemble all 16 c-rows of W^T fp16 (4096 FMA).
//  blocks [256,1280): x -> fp16, 4 uint4 packs/thread, loads batched.
// SMEM floats: sc2 16*1028 | sc1 512 | sc3 8192 = 25152 -> 100608 bytes.
// ---------------------------------------------------------------------------
#define SC2S 1028
#define PREP_DYN_BYTES ((16 * SC2S + 512 + 8192) * 4)   // 100608

__global__ void prep_kernel(const float* __restrict__ x,
                            const float* __restrict__ c1,
                            const float* __restrict__ c2,
                            const float* __restrict__ c3) {
    extern __shared__ __align__(16) float sdyn[];
    const int tid = threadIdx.x;

    if (blockIdx.x >= 256) {
        // ---- x conversion: 1024 blocks x 256 thr x 4 uint4 packs ----
        const size_t p0 = (size_t)(blockIdx.x - 256) * 1024 + tid;
        float4 v[8];
#pragma unroll
        for (int u = 0; u < 4; ++u) {
            const size_t p = p0 + (size_t)u * 256;
            v[u * 2 + 0] = reinterpret_cast<const float4*>(x)[p * 2 + 0];
            v[u * 2 + 1] = reinterpret_cast<const float4*>(x)[p * 2 + 1];
        }
#pragma unroll
        for (int u = 0; u < 4; ++u) {
            uint4 o;
            o.x = h2_as_u32(__floats2half2_rn(v[u * 2].x,     v[u * 2].y));
            o.y = h2_as_u32(__floats2half2_rn(v[u * 2].z,     v[u * 2].w));
            o.z = h2_as_u32(__floats2half2_rn(v[u * 2 + 1].x, v[u * 2 + 1].y));
            o.w = h2_as_u32(__floats2half2_rn(v[u * 2 + 1].z, v[u * 2 + 1].w));
            reinterpret_cast<uint4*>(g_xh)[p0 + (size_t)u * 256] = o;
        }
        return;
    }

    // ---- fused w12 + assemble: CTA per (i,j), thread per (a,b) ----
    const int ij = blockIdx.x;
    const int i = ij >> 4, j = ij & 15;
    const int a = tid >> 4, b = tid & 15;

    float* sc2 = sdyn;                       // [16][SC2S]
    float* sc1 = sdyn + 16 * SC2S;           // [512]
    float* sc3 = sc1 + 512;                  // [8192] = full c3

    // stage c2 j-slice: 16 jb-rows x 1024 floats (4096 float4)
    {
        const float4* src = reinterpret_cast<const float4*>(c2 + (size_t)j * 16384);
#pragma unroll
        for (int u = 0; u < 16; ++u) {
            const int e = u * 256 + tid;              // float4 idx 0..4095
            const int bb = e >> 8, rest = e & 255;    // 256 float4 per jb row
            reinterpret_cast<float4*>(sc2 + bb * SC2S)[rest] = src[e];
        }
    }
    // stage c1 i-slice: 512 floats
    if (tid < 128) {
        reinterpret_cast<float4*>(sc1)[tid] =
            reinterpret_cast<const float4*>(c1 + (size_t)i * 512)[tid];
    }
    // stage c3: FULL [kz][c][q] = 8192 floats (2048 float4)
    {
        const float4* c3g = reinterpret_cast<const float4*>(c3);
        float4* dst = reinterpret_cast<float4*>(sc3);
#pragma unroll
        for (int u = 0; u < 8; ++u)
            dst[u * 256 + tid] = c3g[u * 256 + tid];
    }
    __syncthreads();

    // W12[q] = sum_p c1[ia][p] * c2[jb][p][q]   (registers, 1024 FMA)
    float w12v[32];
#pragma unroll
    for (int q = 0; q < 32; ++q) w12v[q] = 0.f;
    {
        const float* c1row = sc1 + a * 32;            // broadcast reads
        const float* c2row = sc2 + b * SC2S;          // phase-conflict-free
#pragma unroll
        for (int p = 0; p < 32; ++p) {
            const float cp = c1row[p];
            const float4* c2q = reinterpret_cast<const float4*>(c2row + p * 32);
#pragma unroll
            for (int q4 = 0; q4 < 8; ++q4) {
                float4 w = c2q[q4];
                w12v[q4 * 4 + 0] = fmaf(cp, w.x, w12v[q4 * 4 + 0]);
                w12v[q4 * 4 + 1] = fmaf(cp, w.y, w12v[q4 * 4 + 1]);
                w12v[q4 * 4 + 2] = fmaf(cp, w.z, w12v[q4 * 4 + 2]);
                w12v[q4 * 4 + 3] = fmaf(cp, w.w, w12v[q4 * 4 + 3]);
            }
        }
    }

    // assemble all 16 c-rows: wh[(ab*16+c)][ij*16+kz]
    const float4* sc3v = reinterpret_cast<const float4*>(sc3);
    const float4* w12q = reinterpret_cast<const float4*>(w12v);
#pragma unroll 1
    for (int c = 0; c < 16; ++c) {
        float acc[16];
#pragma unroll
        for (int kz = 0; kz < 16; ++kz) acc[kz] = 0.f;
#pragma unroll
        for (int q4 = 0; q4 < 8; ++q4) {
            const float4 w = w12q[q4];
#pragma unroll
            for (int kz = 0; kz < 16; ++kz) {
                float4 cv = sc3v[(kz * 16 + c) * 8 + q4];   // warp broadcast
                acc[kz] = fmaf(w.x, cv.x, acc[kz]);
                acc[kz] = fmaf(w.y, cv.y, acc[kz]);
                acc[kz] = fmaf(w.z, cv.z, acc[kz]);
                acc[kz] = fmaf(w.w, cv.w, acc[kz]);
            }
        }
        __half2 hv[8];
#pragma unroll
        for (int u = 0; u < 8; ++u)
            hv[u] = __floats2half2_rn(acc[u * 2], acc[u * 2 + 1]);
        __half* dst = g_wh + (size_t)(tid * 16 + c) * KDIM + ij * 16;
        uint4 o0, o1;
        memcpy(&o0, &hv[0], 16);
        memcpy(&o1, &hv[4], 16);
        reinterpret_cast<uint4*>(dst)[0] = o0;
        reinterpret_cast<uint4*>(dst)[1] = o1;
    }
}

// ---------------------------------------------------------------------------
// GEMM: single-product fp16 (byte-identical to the measured 242.7us floor).
// CTA tile 128x128, 4 warps (2m x 2n), warp tile 64x64, BK=64,
// 3-stage cp.async ring, one sync/stage, 2 CTAs/SM.
// SMEM rows: 128B data + 16B pad = 144B (conflict-free ldmatrix).
// ---------------------------------------------------------------------------
#define BM 128
#define BN 128
#define ROWB 144
#define ARR_BYTES (128 * ROWB)            // 18432
#define STAGE_BYTES (2 * ARR_BYTES)       // xh | wh = 36864
#define STAGES 3
#define DYN_BYTES (STAGES * STAGE_BYTES)  // 110592

__global__ __launch_bounds__(128, 2)
void tt_gemm_f16(const float* __restrict__ bias, float* __restrict__ C) {
    extern __shared__ __align__(16) char dyn[];
    const uint32_t dynU = smem_u32(dyn);

    const int tid = threadIdx.x;
    const int wid = tid >> 5;
    const int lid = tid & 31;
    const int warp_m = wid & 1;      // 2 m-groups of 64 rows
    const int warp_n = wid >> 1;     // 2 n-groups of 64 cols
    const int m0 = blockIdx.y * BM;
    const int n0 = blockIdx.x * BN;

    const char* xh = (const char*)g_xh;
    const char* wh = (const char*)g_wh;

    uint32_t sOff[8];
    size_t gAOff[8], gBOff[8];
#pragma unroll
    for (int u = 0; u < 8; ++u) {
        const int ci = u * 128 + tid;
        const int r = ci >> 3, ch = (ci & 7) * 16;
        sOff[u] = (uint32_t)(r * ROWB + ch);
        gAOff[u] = (size_t)(m0 + r) * (KDIM * 2) + ch;
        gBOff[u] = (size_t)(n0 + r) * (KDIM * 2) + ch;
    }

    float acc[4][8][4];
#pragma unroll
    for (int a = 0; a < 4; ++a)
#pragma unroll
        for (int b = 0; b < 8; ++b)
#pragma unroll
            for (int c = 0; c < 4; ++c) acc[a][b][c] = 0.f;

    const uint32_t lmRow = (uint32_t)(lid & 15);
    const uint32_t lmCol = (uint32_t)((lid >> 4) * 16);
    const uint32_t aLM = (uint32_t)((warp_m * 64 + lmRow) * ROWB) + lmCol;
    const uint32_t bLM = (uint32_t)((warp_n * 64 + lmRow) * ROWB) + lmCol;

    auto load_stage = [&](int kt) {
        const uint32_t sb = dynU + (uint32_t)(kt % STAGES) * STAGE_BYTES;
        const size_t ko = (size_t)kt * 128;   // 64 halves = 128B along k
#pragma unroll
        for (int u = 0; u < 8; ++u) {
            cp_async16(sb + sOff[u],             xh + gAOff[u] + ko);
            cp_async16(sb + ARR_BYTES + sOff[u], wh + gBOff[u] + ko);
        }
    };

    load_stage(0); CP_COMMIT();
    load_stage(1); CP_COMMIT();

    const int numK = KDIM / 64;      // 64 stages
    for (int kt = 0; kt < numK; ++kt) {
        CP_WAIT1();
        __syncthreads();             // publish stage kt

        if (kt + 2 < numK) load_stage(kt + 2);
        CP_COMMIT();

        const uint32_t sb = dynU + (uint32_t)(kt % STAGES) * STAGE_BYTES;
        const uint32_t aB = sb + aLM;
        const uint32_t bB = sb + ARR_BYTES + bLM;

#pragma unroll
        for (int ks = 0; ks < 4; ++ks) {             // four k16 steps
            const uint32_t kb = (uint32_t)(ks * 32); // 16 halves = 32B
            uint32_t ah[4][4];
#pragma unroll
            for (int mt = 0; mt < 4; ++mt)
                ldmx4(ah[mt], aB + (uint32_t)(mt * 16 * ROWB) + kb);
            uint32_t bh[4][4];
#pragma unroll
            for (int bt = 0; bt < 4; ++bt)
                ldmx4(bh[bt], bB + (uint32_t)(bt * 16 * ROWB) + kb);
#pragma unroll
            for (int mt = 0; mt < 4; ++mt) {
#pragma unroll
                for (int nt = 0; nt < 8; ++nt) {
                    const int bt = nt >> 1, o = nt & 1;
                    mma_f16(acc[mt][nt], ah[mt], bh[bt][o], bh[bt][o + 2]);
                }
            }
        }
    }

    // epilogue: bias + relu, float2 stores
    const int g = lid >> 2, t4 = lid & 3;
    float bb[8][2];
#pragma unroll
    for (int nt = 0; nt < 8; ++nt) {
        const int col = n0 + warp_n * 64 + nt * 8 + t4 * 2;
        bb[nt][0] = bias[col];
        bb[nt][1] = bias[col + 1];
    }
#pragma unroll
    for (int mt = 0; mt < 4; ++mt) {
        const int row = m0 + warp_m * 64 + mt * 16 + g;
#pragma unroll
        for (int nt = 0; nt < 8; ++nt) {
            const int col = n0 + warp_n * 64 + nt * 8 + t4 * 2;
            float2 v0, v1;
            v0.x = fmaxf(acc[mt][nt][0] + bb[nt][0], 0.f);
            v0.y = fmaxf(acc[mt][nt][1] + bb[nt][1], 0.f);
            v1.x = fmaxf(acc[mt][nt][2] + bb[nt][0], 0.f);
            v1.y = fmaxf(acc[mt][nt][3] + bb[nt][1], 0.f);
            *reinterpret_cast<float2*>(&C[(size_t)row * NDIM + col]) = v0;
            *reinterpret_cast<float2*>(&C[(size_t)(row + 8) * NDIM + col]) = v1;
        }
    }
}

// ---------------------------------------------------------------------------
// Launch
// ---------------------------------------------------------------------------
extern "C" void kernel_launch(void* const* d_in, const int* in_sizes, int n_in,
                              void* d_out, int out_size) {
    const float* x    = (const float*)d_in[0];
    const float* c1   = (const float*)d_in[1];
    const float* c2   = (const float*)d_in[2];
    const float* c3   = (const float*)d_in[3];
    const float* bias = (const float*)d_in[4];
    float* out = (float*)d_out;
    (void)in_sizes; (void)n_in; (void)out_size;

    cudaFuncSetAttribute(prep_kernel,
                         cudaFuncAttributeMaxDynamicSharedMemorySize, PREP_DYN_BYTES);
    cudaFuncSetAttribute(tt_gemm_f16,
                         cudaFuncAttributeMaxDynamicSharedMemorySize, DYN_BYTES);

    prep_kernel<<<256 + 1024, 256, PREP_DYN_BYTES>>>(x, c1, c2, c3);

    dim3 grid(NDIM / BN, BATCH / BM);   // (32, 16) = 512 CTAs
    tt_gemm_f16<<<grid, 128, DYN_BYTES>>>(bias, out);
}